// round 5
// baseline (speedup 1.0000x reference)
#include <cuda_runtime.h>
#include <math.h>

#define NODE  400
#define TRS   40
#define STEPS 10
#define NSTEP (TRS * STEPS)
#define OUTN  64
#define DMAXC 500
#define KBUF  512
#define ACCN  544      // >= NSTEP + 128 + 1
#define DTF   0.1f
#define LOG2E 1.4426950408889634f

#define NPB   8        // nodes (warps) per sim block
// per-node dynamic smem slot layout (bytes)
#define OFF_ACC  0                       // float4[ACCN]  = 8704
#define OFF_KSM  (ACCN * 16)             // float4[KBUF]  = 8192
#define OFF_H0   (OFF_KSM + KBUF * 16)   // float[KBUF]   = 2048
#define OFF_ES   (OFF_H0 + KBUF * 4)     // float[NSTEP]  = 1600
#define NODE_SMEM (OFF_ES + NSTEP * 4)   // 20544
#define SIM_SMEM (NODE_SMEM * NPB)       // 164352

// ---- persistent scratch (device globals; no allocation) ----
__device__ float  g_rowSS[3 * NODE];
__device__ float  g_invnorm[3];       // [b, f, l]
__device__ float  g_rs[NODE * 3];     // raw row sums [b,f,l] per node
__device__ float4 g_K4[NODE * KBUF];  // per-node delay histogram (x=b,y=f,z=l)
__device__ int    g_ndmax[NODE];
__device__ float  g_colmean[NODE];
__device__ float  g_Vsnap[TRS * NODE];

__device__ __forceinline__ float reluf(float x) { return x > 0.f ? x : 0.f; }
__device__ __forceinline__ float ex2f(float x) { float y; asm("ex2.approx.f32 %0,%1;" : "=f"(y) : "f"(x)); return y; }
__device__ __forceinline__ float rcpf(float x) { float y; asm("rcp.approx.f32 %0,%1;" : "=f"(y) : "f"(x)); return y; }

// ---------------------------------------------------------------------------
// PREP: per-node weights, row sums, row sum-of-squares, delay histogram, dmax.
// ---------------------------------------------------------------------------
__global__ void __launch_bounds__(128) prep_kernel(
    const float* __restrict__ wbb, const float* __restrict__ wff,
    const float* __restrict__ wll, const float* __restrict__ sc,
    const float* __restrict__ dist, const float* __restrict__ theta)
{
    int i = blockIdx.x;
    int tid = threadIdx.x;
    int w = tid >> 5, lane = tid & 31;
    __shared__ float4 w4[NODE];        // 6.4 KB
    __shared__ int    dly[NODE];       // 1.6 KB
    __shared__ float4 H[4][KBUF];      // 32 KB private histograms
    __shared__ float  red[6][128];     // 3 KB
    __shared__ int    dred[4];

    float mu = 0.1f + reluf(theta[20]);
    float ssb = 0.f, ssf = 0.f, ssl = 0.f, rb = 0.f, rf = 0.f, rl = 0.f;
    for (int j = tid; j < NODE; j += 128) {
        float scij = sc[i * NODE + j];
        float wb = __expf(wbb[i * NODE + j]) * scij;
        float wf = __expf(wff[i * NODE + j]) * scij;
        float wl = 0.5f * (__expf(wll[i * NODE + j]) * scij +
                           __expf(wll[j * NODE + i]) * sc[j * NODE + i]);
        int d = (int)(dist[i * NODE + j] / mu);   // accurate division like reference
        if (d < 0) d = 0;
        if (d > DMAXC - 1) d = DMAXC - 1;
        w4[j] = make_float4(wb, wf, wl, 0.f);
        dly[j] = d;
        ssb += wb * wb; ssf += wf * wf; ssl += wl * wl;
        rb += wb; rf += wf; rl += wl;
    }
    for (int d = tid; d < KBUF; d += 128) {
        float4 z = make_float4(0.f, 0.f, 0.f, 0.f);
        H[0][d] = z; H[1][d] = z; H[2][d] = z; H[3][d] = z;
    }
    red[0][tid] = ssb; red[1][tid] = ssf; red[2][tid] = ssl;
    red[3][tid] = rb;  red[4][tid] = rf;  red[5][tid] = rl;
    __syncthreads();
    for (int off = 64; off; off >>= 1) {
        if (tid < off) {
#pragma unroll
            for (int c = 0; c < 6; c++) red[c][tid] += red[c][tid + off];
        }
        __syncthreads();
    }
    if (tid == 0) {
        g_rowSS[0 * NODE + i] = red[0][0];
        g_rowSS[1 * NODE + i] = red[1][0];
        g_rowSS[2 * NODE + i] = red[2][0];
        g_rs[i * 3 + 0] = red[3][0];
        g_rs[i * 3 + 1] = red[4][0];
        g_rs[i * 3 + 2] = red[5][0];
    }

    // histogram: warp w scans j in [100w, 100w+100); lane owns (d&31)==lane bins
    int dmx = 0;
    int j0 = w * (NODE / 4);
    for (int jj = 0; jj < NODE / 4; jj++) {
        int j = j0 + jj;
        int d = dly[j];
        if ((d & 31) == lane) {
            float4 wv = w4[j];
            H[w][d].x += wv.x; H[w][d].y += wv.y; H[w][d].z += wv.z;
            dmx = d > dmx ? d : dmx;
        }
    }
#pragma unroll
    for (int off = 16; off; off >>= 1) dmx = max(dmx, __shfl_xor_sync(0xffffffffu, dmx, off));
    if (lane == 0) dred[w] = dmx;
    __syncthreads();

    float4* Kg = g_K4 + (size_t)i * KBUF;
    for (int d = tid; d < KBUF; d += 128) {
        float4 a = H[0][d], b = H[1][d], c = H[2][d], e = H[3][d];
        float4 r;
        r.x = ((a.x + b.x) + c.x) + e.x;
        r.y = ((a.y + b.y) + c.y) + e.y;
        r.z = ((a.z + b.z) + c.z) + e.z;
        r.w = 0.f;
        Kg[d] = r;
    }
    if (tid == 0) g_ndmax[i] = max(max(dred[0], dred[1]), max(dred[2], dred[3]));
}

// ---------------------------------------------------------------------------
// P2: finish norms + lm column means
// ---------------------------------------------------------------------------
__global__ void p2_norms(const float* __restrict__ lm)
{
    int t = threadIdx.x;  // 512 threads, 1 block
    __shared__ float red[512];
    for (int c = 0; c < 3; c++) {
        float s = 0.f;
        for (int i = t; i < NODE; i += 512) s += g_rowSS[c * NODE + i];
        red[t] = s;
        __syncthreads();
        for (int off = 256; off; off >>= 1) {
            if (t < off) red[t] += red[t + off];
            __syncthreads();
        }
        if (t == 0) g_invnorm[c] = 1.0f / sqrtf(red[0]);
        __syncthreads();
    }
    if (t < NODE) {
        float s = 0.f;
        for (int o = 0; o < OUTN; o++) s += lm[o * NODE + t];
        g_colmean[t] = s * (1.0f / OUTN);
    }
}

// ---------------------------------------------------------------------------
// SIM: 50 blocks x 256 threads; warp w simulates node blockIdx*8+w out of its
// own dynamic-smem slot. 2 warps/SMSP fill each other's latency bubbles.
// Near taps d<32 live in a rotating register window; far taps d in [32,128)
// scatter-forward into smem Acc; tail d>=128 rare path.
// ---------------------------------------------------------------------------
__global__ void __launch_bounds__(256) sim_kernel(
    const float* __restrict__ ext, const float* __restrict__ hx,
    const float* __restrict__ hE0, const float* __restrict__ theta)
{
    extern __shared__ char dsm[];
    int wid  = threadIdx.x >> 5;
    int lane = threadIdx.x & 31;
    int i = blockIdx.x * NPB + wid;       // node (50*8 = 400 exactly)

    char* base = dsm + wid * NODE_SMEM;
    float4* Acc = (float4*)(base + OFF_ACC);
    float4* Ksm = (float4*)(base + OFF_KSM);
    float*  H0  = (float*) (base + OFF_H0);
    float*  Es  = (float*) (base + OFF_ES);

    const float4* Kg = g_K4 + (size_t)i * KBUF;
    for (int d = lane; d < KBUF; d += 32) Ksm[d] = Kg[d];
    for (int d = lane; d < DMAXC; d += 32) H0[d] = hE0[i * DMAXC + d];
    for (int d = DMAXC + lane; d < KBUF; d += 32) H0[d] = 0.f;
    for (int s = lane; s < ACCN; s += 32) Acc[s] = make_float4(0.f, 0.f, 0.f, 0.f);
    // transpose external input: Es[tr*STEPS+st] for sequential inner reads
    for (int s = lane; s < NSTEP; s += 32) {
        int st = s / TRS, tr = s - st * TRS;
        Es[tr * STEPS + st] = ext[(size_t)i * NSTEP + s];
    }
    __syncwarp();

    int dmax = g_ndmax[i];
    // fold initial history: Acc[tau] = sum_{d>=tau} K[d] * hE0[d-tau]
    for (int tau = lane; tau <= dmax && tau < NSTEP; tau += 32) {
        float aB = 0.f, aF = 0.f, aL = 0.f;
        for (int d = tau; d <= dmax; d++) {
            float h = H0[d - tau];
            float4 Kv = Ksm[d];
            aB = fmaf(Kv.x, h, aB);
            aF = fmaf(Kv.y, h, aF);
            aL = fmaf(Kv.z, h, aL);
        }
        Acc[tau] = make_float4(aB, aF, aL, 0.f);
    }
    __syncwarp();

    int pop = lane % 3;

    // scalar parameters
    float VL = reluf(theta[0]), VI = reluf(theta[1]), VE = reluf(theta[2]), VN = reluf(theta[3]);
    float amg = reluf(theta[4]), VR = reluf(theta[5]), ps = reluf(theta[6]);
    float gL = reluf(theta[7]), invC = rcpf(reluf(theta[8])), kap = reluf(theta[9]);
    float ggE = reluf(theta[10]), ggEsc = reluf(theta[11]);
    float ggI = reluf(theta[12]), ggIsc = reluf(theta[13]);
    float ggN = reluf(theta[14]), ggNsc = reluf(theta[15]);
    float gk  = reluf(theta[16]);
    float kki = reluf(theta[21]) * theta[23];
    float g_lc = reluf(theta[24]), g_fc = reluf(theta[25]), g_bc = reluf(theta[26]);

    float ABc = g_bc * g_invnorm[0], BBc = ABc * g_rs[i * 3 + 0];
    float AFc = g_fc * g_invnorm[1], BFc = AFc * g_rs[i * 3 + 1];
    float ALc = g_lc * g_invnorm[2], BLc = ALc * g_rs[i * 3 + 2];

    // per-lane population constants
    float cE, cI, cN, mU, mLr, Al, Bl;
    if (pop == 0)      { cE = ggE;   cI = ggI;   cN = ggN;   mU = kki; mLr = 1.f; Al = ALc; Bl = BLc; }
    else if (pop == 1) { cE = ggEsc; cI = ggIsc; cN = ggNsc; mU = 0.f; mLr = 0.f; Al = ABc; Bl = BBc; }
    else               { cE = gk;    cI = ggI;   cN = ggN;   mU = kki; mLr = 0.f; Al = AFc; Bl = BFc; }

    float nps2 = -ps * LOG2E, cs = ps * VR * LOG2E;
    float namg2 = -amg * LOG2E;

    float V  = hx[i * 12 + pop * 4 + 0];
    float gE = hx[i * 12 + pop * 4 + 1];
    float gI = hx[i * 12 + pop * 4 + 2];
    float gN = hx[i * 12 + pop * 4 + 3];

    // near taps (register, constant per lane) + far taps
    float4 Kn = Ksm[lane];
    float4 K1 = Ksm[lane + 32], K2 = Ksm[lane + 64], K3 = Ksm[lane + 96];
    bool tail = (dmax >= 128);

    float PB = 0.f, PF = 0.f, PL = 0.f;   // near-window partials: lane l = slot t+l
    float dtk = DTF * kap;
    int t = 0;
    for (int tr = 0; tr < TRS; tr++) {
        const float* Etr = Es + tr * STEPS;
#pragma unroll
        for (int st = 0; st < STEPS; st++) {
            float s_ = rcpf(1.0f + ex2f(fmaf(nps2, V, cs)));
            float s0 = __shfl_sync(0xffffffffu, s_, 0);
            float s1 = __shfl_sync(0xffffffffu, s_, 1);
            float s2 = __shfl_sync(0xffffffffu, s_, 2);

            float mN = rcpf(fmaf(0.2f, ex2f(namg2 * V), 1.0f));
            float dV = (fmaf(gL, -VL - V,
                        fmaf(gE, VE - V,
                        fmaf(gI, -VI - V, (gN * mN) * (VN - V))))) * invC;

            // slot-t value: fold+far (smem) + near partial (lane 0's register)
            float4 fa = Acc[t];
            float aPB = __shfl_sync(0xffffffffu, PB, 0);
            float aPF = __shfl_sync(0xffffffffu, PF, 0);
            float aPL = __shfl_sync(0xffffffffu, PL, 0);
            float a = (pop == 0) ? (fa.z + aPL) : ((pop == 1) ? (fa.x + aPB) : (fa.y + aPF));
            float lr = fmaf(Al, a, -(Bl * s2));

            float u = Etr[st];
            float se = (pop == 0) ? s2 : s0;
            float exc = fmaf(cE, se, lr);
            exc = fmaf(mU, u, exc);
            float nm = fmaf(cN, se, mLr * lr);
            float inh = cI * s1;

            V  = fmaf(DTF, dV, V);
            gE = fmaf(dtk, exc - gE, gE);
            gI = fmaf(dtk, inh - gI, gI);
            gN = fmaf(dtk, nm  - gN, gN);

            // rotate near window down by one slot; lane 31 becomes fresh slot t+32
            float rB = __shfl_down_sync(0xffffffffu, PB, 1);
            float rF = __shfl_down_sync(0xffffffffu, PF, 1);
            float rL = __shfl_down_sync(0xffffffffu, PL, 1);
            bool fresh = (lane == 31);
            PB = fmaf(Kn.x, s2, fresh ? 0.f : rB);
            PF = fmaf(Kn.y, s2, fresh ? 0.f : rF);
            PL = fmaf(Kn.z, s2, fresh ? 0.f : rL);

            // far scatter (read >=33 steps later; synced per trial)
            int sb = t + 1 + lane;
            float4 A1 = Acc[sb + 32];
            A1.x = fmaf(K1.x, s2, A1.x); A1.y = fmaf(K1.y, s2, A1.y); A1.z = fmaf(K1.z, s2, A1.z);
            Acc[sb + 32] = A1;
            float4 A2 = Acc[sb + 64];
            A2.x = fmaf(K2.x, s2, A2.x); A2.y = fmaf(K2.y, s2, A2.y); A2.z = fmaf(K2.z, s2, A2.z);
            Acc[sb + 64] = A2;
            float4 A3 = Acc[sb + 96];
            A3.x = fmaf(K3.x, s2, A3.x); A3.y = fmaf(K3.y, s2, A3.y); A3.z = fmaf(K3.z, s2, A3.z);
            Acc[sb + 96] = A3;
            if (tail) {
                int dend = dmax;
                if (dend > ACCN - 2 - t) dend = ACCN - 2 - t;  // never-read slots skipped
                for (int d = 128 + lane; d <= dend; d += 32) {
                    float4 Kv = Ksm[d];
                    float4 Av = Acc[t + 1 + d];
                    Av.x = fmaf(Kv.x, s2, Av.x); Av.y = fmaf(Kv.y, s2, Av.y); Av.z = fmaf(Kv.z, s2, Av.z);
                    Acc[t + 1 + d] = Av;
                }
            }
            t++;
        }
        __syncwarp();
        if (lane == 2) g_Vsnap[tr * NODE + i] = V;   // population 2's V
    }
}

// ---------------------------------------------------------------------------
// EEG: warp per (trial, output); dual dot folds the column-mean subtraction.
// 2560 warps -> all load latency hidden by parallelism.
// ---------------------------------------------------------------------------
__global__ void __launch_bounds__(256) eeg_kernel(
    const float* __restrict__ lm, const float* __restrict__ theta,
    float* __restrict__ out)
{
    int wpair = blockIdx.x * 8 + (threadIdx.x >> 5);   // 0..2559
    int lane = threadIdx.x & 31;
    int tr = wpair >> 6;
    int o  = wpair & 63;
    const float* Vs   = g_Vsnap + tr * NODE;
    const float* lrow = lm + o * NODE;

    float a0 = 0.f, a1 = 0.f, m0 = 0.f, m1 = 0.f;
#pragma unroll
    for (int k = 0; k < 7; k++) {          // 7*64 = 448 >= 400, last partial
        int i1 = lane + k * 64;
        int i2 = i1 + 32;
        if (i1 < NODE) {
            float v = Vs[i1];
            a0 = fmaf(lrow[i1], v, a0);
            m0 = fmaf(g_colmean[i1], v, m0);
        }
        if (i2 < NODE) {
            float v = Vs[i2];
            a1 = fmaf(lrow[i2], v, a1);
            m1 = fmaf(g_colmean[i2], v, m1);
        }
    }
    float acc = a0 + a1, m = m0 + m1;
#pragma unroll
    for (int off = 16; off; off >>= 1) {
        acc += __shfl_xor_sync(0xffffffffu, acc, off);
        m   += __shfl_xor_sync(0xffffffffu, m, off);
    }
    if (lane == 0) {
        float cy0 = theta[22], y0v = theta[19];
        out[tr * OUTN + o] = cy0 * (acc - m) - y0v;
    }
}

// ---------------------------------------------------------------------------
extern "C" void kernel_launch(void* const* d_in, const int* in_sizes, int n_in,
                              void* d_out, int out_size)
{
    const float* ext   = (const float*)d_in[0];
    const float* hx    = (const float*)d_in[1];
    const float* hE    = (const float*)d_in[2];
    const float* sc    = (const float*)d_in[3];
    const float* dist  = (const float*)d_in[4];
    const float* wbb   = (const float*)d_in[5];
    const float* wff   = (const float*)d_in[6];
    const float* wll   = (const float*)d_in[7];
    const float* lm    = (const float*)d_in[8];
    const float* theta = (const float*)d_in[9];
    float* out = (float*)d_out;

    cudaFuncSetAttribute(sim_kernel, cudaFuncAttributeMaxDynamicSharedMemorySize, SIM_SMEM);

    prep_kernel<<<NODE, 128>>>(wbb, wff, wll, sc, dist, theta);
    p2_norms<<<1, 512>>>(lm);
    sim_kernel<<<NODE / NPB, 256, SIM_SMEM>>>(ext, hx, hE, theta);
    eeg_kernel<<<(TRS * OUTN) / 8, 256>>>(lm, theta, out);
}